// round 1
// baseline (speedup 1.0000x reference)
#include <cuda_runtime.h>
#include <cuda_bf16.h>

#define TT    100000
#define HDIM  16
#define UDIM  7
#define HID   64
#define XDIM  (HDIM + UDIM)

// Scratch (static device globals — no allocation at runtime).
__device__ float g_V[(TT + 1) * HID];        // V[t][j] = b1[j] + W1_u[j] . u_t
__device__ float g_htraj[(TT + 1) * HDIM];   // h_t trajectory (h_traj[0] = h0)

// ---------------------------------------------------------------------------
// Kernel 1: precompute V[t][j] = b1[j] + sum_c W1[j][HDIM+c] * U[t][c]
// Fully parallel over t. blockDim = (64, 4).
// ---------------------------------------------------------------------------
__global__ void pre_kernel(const float* __restrict__ U,
                           const float* __restrict__ W1,
                           const float* __restrict__ b1) {
    int j = threadIdx.x;                       // hidden unit 0..63
    int t = blockIdx.x * blockDim.y + threadIdx.y;
    if (t >= TT) return;
    float acc = b1[j];
    const float* u = U + t * UDIM;
    const float* w = W1 + j * XDIM + HDIM;
#pragma unroll
    for (int c = 0; c < UDIM; c++)
        acc += w[c] * __ldg(u + c);
    g_V[t * HID + j] = acc;
}

// ---------------------------------------------------------------------------
// Kernel 2: the sequential scan. One CTA, 64 threads (2 warps).
// Lane j owns hidden unit j for z1/z2. For dh: i = j>>2, quarter q = j&3.
// Weights register-resident. z1/z2/h exchanged through shared memory.
// ---------------------------------------------------------------------------
__global__ void __launch_bounds__(64, 1)
scan_kernel(const float* __restrict__ W1,
            const float* __restrict__ W2,
            const float* __restrict__ b2,
            const float* __restrict__ W3,
            const float* __restrict__ b3,
            const float* __restrict__ h0,
            float* __restrict__ out) {
    const int j   = threadIdx.x;
    const int q   = j & 3;
    const int i16 = j >> 2;

    __shared__ __align__(16) float z1s[HID];
    __shared__ __align__(16) float z2s[HID];
    __shared__ __align__(16) float hs[HDIM];

    // --- load weights into registers (one-time) ---
    float w1h[HDIM];
#pragma unroll
    for (int c = 0; c < HDIM; c++) w1h[c] = W1[j * XDIM + c];

    float w2r[HID];
#pragma unroll
    for (int c = 0; c < HID; c++) w2r[c] = W2[j * HID + c];
    const float b2j = b2[j];

    float w3q[16];
#pragma unroll
    for (int m = 0; m < 16; m++) w3q[m] = W3[i16 * HID + q * 16 + m];
    const float b3i = (q == 0) ? b3[i16] : 0.0f;

    float h[HDIM];
#pragma unroll
    for (int c = 0; c < HDIM; c++) h[c] = h0[c];

    if (j < HDIM) g_htraj[j] = h[j];          // h_traj[0] = h0

    const float dt = (float)(5.0 / 60.0);

    const float* vp = g_V + HID + j;           // points at V[t+1][j]
    float vcur = g_V[j];                       // V[0][j]

#pragma unroll 1
    for (int t = 0; t < TT; t++) {
        // prefetch next V early — consumed ~500 cycles later
        float vnext = __ldg(vp);
        vp += HID;

        // ---- z1 = tanh(W1_h . h + V[t][j]) ----
        float a0 = vcur, a1 = 0.f, a2 = 0.f, a3 = 0.f;
#pragma unroll
        for (int c = 0; c < HDIM; c += 4) {
            a0 += w1h[c + 0] * h[c + 0];
            a1 += w1h[c + 1] * h[c + 1];
            a2 += w1h[c + 2] * h[c + 2];
            a3 += w1h[c + 3] * h[c + 3];
        }
        float z1 = tanhf((a0 + a1) + (a2 + a3));
        z1s[j] = z1;
        __syncthreads();

        // ---- z2 = tanh(W2 . z1 + b2) ----
        float c0 = b2j, c1 = 0.f, c2 = 0.f, c3 = 0.f;
        const float4* z14 = (const float4*)z1s;
#pragma unroll
        for (int c = 0; c < 16; c++) {
            float4 z = z14[c];
            c0 += w2r[4 * c + 0] * z.x;
            c1 += w2r[4 * c + 1] * z.y;
            c2 += w2r[4 * c + 2] * z.z;
            c3 += w2r[4 * c + 3] * z.w;
        }
        float z2 = tanhf((c0 + c1) + (c2 + c3));
        z2s[j] = z2;
        __syncthreads();

        // ---- dh[i16] partial over quarter q, then 4-lane butterfly ----
        float p0 = 0.f, p1 = 0.f, p2 = 0.f, p3 = 0.f;
        const float4* z24 = (const float4*)(z2s + q * 16);
#pragma unroll
        for (int c = 0; c < 4; c++) {
            float4 z = z24[c];
            p0 += w3q[4 * c + 0] * z.x;
            p1 += w3q[4 * c + 1] * z.y;
            p2 += w3q[4 * c + 2] * z.z;
            p3 += w3q[4 * c + 3] * z.w;
        }
        float p = (p0 + p1) + (p2 + p3);
        p += __shfl_xor_sync(0xffffffffu, p, 1);
        p += __shfl_xor_sync(0xffffffffu, p, 2);

        if (q == 0) {
            float hn = h[i16] + dt * (p + b3i);
            hs[i16] = hn;
            g_htraj[(t + 1) * HDIM + i16] = hn;   // fire-and-forget
        }
        __syncthreads();

        // ---- broadcast h back to all lanes ----
        const float4* h4 = (const float4*)hs;
#pragma unroll
        for (int c = 0; c < 4; c++) {
            float4 hv = h4[c];
            h[4 * c + 0] = hv.x;
            h[4 * c + 1] = hv.y;
            h[4 * c + 2] = hv.z;
            h[4 * c + 3] = hv.w;
        }
        vcur = vnext;
    }

    // final state hT -> out[3T .. 3T+16)
    if (j < HDIM) out[3 * TT + j] = h[j];
}

// ---------------------------------------------------------------------------
// Kernel 3: readouts from the stored trajectory. Fully parallel over t.
// delay[t] = h_t.wd + bd ; taxi[t] = h_t.wt + bt ; loglam[t] = h_t.wc + bc
// ---------------------------------------------------------------------------
__global__ void readout_kernel(const float* __restrict__ wd, const float* __restrict__ bd,
                               const float* __restrict__ wt, const float* __restrict__ bt,
                               const float* __restrict__ wc, const float* __restrict__ bc,
                               float* __restrict__ out) {
    int t = blockIdx.x * blockDim.x + threadIdx.x;
    if (t >= TT) return;

    float vd[HDIM], vt[HDIM], vc[HDIM];
#pragma unroll
    for (int k = 0; k < HDIM; k++) {
        vd[k] = __ldg(wd + k);
        vt[k] = __ldg(wt + k);
        vc[k] = __ldg(wc + k);
    }
    float d = __ldg(bd), x = __ldg(bt), c = __ldg(bc);
    const float4* h4 = (const float4*)(g_htraj + t * HDIM);
#pragma unroll
    for (int k = 0; k < 4; k++) {
        float4 hv = h4[k];
        d += hv.x * vd[4 * k] + hv.y * vd[4 * k + 1] + hv.z * vd[4 * k + 2] + hv.w * vd[4 * k + 3];
        x += hv.x * vt[4 * k] + hv.y * vt[4 * k + 1] + hv.z * vt[4 * k + 2] + hv.w * vt[4 * k + 3];
        c += hv.x * vc[4 * k] + hv.y * vc[4 * k + 1] + hv.z * vc[4 * k + 2] + hv.w * vc[4 * k + 3];
    }
    out[t]          = d;
    out[TT + t]     = x;
    out[2 * TT + t] = c;
}

// ---------------------------------------------------------------------------
extern "C" void kernel_launch(void* const* d_in, const int* in_sizes, int n_in,
                              void* d_out, int out_size) {
    const float* U  = (const float*)d_in[0];
    const float* W1 = (const float*)d_in[1];
    const float* b1 = (const float*)d_in[2];
    const float* W2 = (const float*)d_in[3];
    const float* b2 = (const float*)d_in[4];
    const float* W3 = (const float*)d_in[5];
    const float* b3 = (const float*)d_in[6];
    const float* wd = (const float*)d_in[7];
    const float* bd = (const float*)d_in[8];
    const float* wt = (const float*)d_in[9];
    const float* bt = (const float*)d_in[10];
    const float* wc = (const float*)d_in[11];
    const float* bc = (const float*)d_in[12];
    const float* h0 = (const float*)d_in[13];
    float* out = (float*)d_out;

    dim3 pb(HID, 4);
    pre_kernel<<<(TT + 3) / 4, pb>>>(U, W1, b1);
    scan_kernel<<<1, HID>>>(W1, W2, b2, W3, b3, h0, out);
    readout_kernel<<<(TT + 127) / 128, 128>>>(wd, bd, wt, bt, wc, bc, out);
}